// round 1
// baseline (speedup 1.0000x reference)
#include <cuda_runtime.h>
#include <math.h>

// Problem constants
#define NMAX 100000          // N_ACT
#define NATOM 64

// Scratch (static device globals: allocation-free)
__device__ float d_lf[NMAX];     // policy logits
__device__ float d_lv[NMAX];     // value logits
__device__ float d_red[768];     // [0:256) block max, [256:512) block vsum, [512:768) block expsum
__device__ float d_scal[4];      // 0: gmax, 1: vsum, 2: lse

// ---------------------------------------------------------------------------
// Process two atoms of one action (one lane's work). Outputs r1/g1 for the
// FIRST atom of the pair (used at t==0/sub==0 to capture atom-0 for the
// value-head exclusion).
// ---------------------------------------------------------------------------
__device__ __forceinline__ void proc_pair(
    const float* __restrict__ S, const float4* __restrict__ R4,
    const float* __restrict__ M,
    int a1, int a2,
    const float (* __restrict__ sWe1)[12], const float* __restrict__ sbe1,
    const float (* __restrict__ sWe2)[12], const float* __restrict__ sbe2,
    float A[2][4], float Bm[4][10], float r1[4], float g1[10])
{
    float s1 = S[a1], s2 = S[a2];
    float4 q1 = R4[a1], q2 = R4[a2];
    r1[0] = s1 * q1.x; r1[1] = s1 * q1.y; r1[2] = s1 * q1.z; r1[3] = s1 * q1.w;
    float r2[4] = { s2 * q2.x, s2 * q2.y, s2 * q2.z, s2 * q2.w };

    float m1[3], m2[3];
    m1[0] = s1 * M[a1 * 3 + 0]; m1[1] = s1 * M[a1 * 3 + 1]; m1[2] = s1 * M[a1 * 3 + 2];
    m2[0] = s2 * M[a2 * 3 + 0]; m2[1] = s2 * M[a2 * 3 + 1]; m2[2] = s2 * M[a2 * 3 + 2];

    float h1[10], h2[10];
    #pragma unroll
    for (int j = 0; j < 10; j++) { float b = sbe1[j]; h1[j] = b; h2[j] = b; }
    #pragma unroll
    for (int s = 0; s < 3; s++) {
        #pragma unroll
        for (int j = 0; j < 10; j++) {
            float w = sWe1[s][j];
            h1[j] += m1[s] * w;
            h2[j] += m2[s] * w;
        }
    }
    #pragma unroll
    for (int j = 0; j < 10; j++) { h1[j] = fmaxf(h1[j], 0.f); h2[j] = fmaxf(h2[j], 0.f); }

    float g2[10];
    #pragma unroll
    for (int n = 0; n < 10; n++) { float b = sbe2[n]; g1[n] = b; g2[n] = b; }
    #pragma unroll
    for (int j = 0; j < 10; j++) {
        float a = h1[j], b = h2[j];
        #pragma unroll
        for (int n = 0; n < 10; n++) {
            float w = sWe2[j][n];
            g1[n] += a * w;
            g2[n] += b * w;
        }
    }

    #pragma unroll
    for (int k = 0; k < 2; k++)
        #pragma unroll
        for (int l = 0; l < 4; l++)
            A[k][l] += g1[k] * r1[l] + g2[k] * r2[l];

    #pragma unroll
    for (int l = 0; l < 4; l++)
        #pragma unroll
        for (int n = 0; n < 10; n++)
            Bm[l][n] += r1[l] * g1[n] + r2[l] * g2[n];
}

// ---------------------------------------------------------------------------
// Main kernel: 128 threads/block, 4 lanes per action -> 32 actions/block.
// ---------------------------------------------------------------------------
__global__ void __launch_bounds__(128)
desc_main_kernel(
    const float* __restrict__ Smat, const float* __restrict__ Rraw,
    const float* __restrict__ Msk,
    const float* __restrict__ We1, const float* __restrict__ be1,
    const float* __restrict__ We2, const float* __restrict__ be2,
    const float* __restrict__ Wf1, const float* __restrict__ bf1,
    const float* __restrict__ Wf2, const float* __restrict__ bf2,
    const float* __restrict__ Wf3, const float* __restrict__ bf3,
    const float* __restrict__ Wv1, const float* __restrict__ bv1,
    const float* __restrict__ Wv2, const float* __restrict__ bv2,
    const float* __restrict__ Wv3, const float* __restrict__ bv3,
    int n_act)
{
    __shared__ __align__(16) float sWe1[3][12];
    __shared__ __align__(16) float sbe1[12];
    __shared__ __align__(16) float sWe2[10][12];
    __shared__ __align__(16) float sbe2[12];
    __shared__ __align__(16) float sW1[2][20 * 32];
    __shared__ __align__(16) float sb1[2][32];
    __shared__ __align__(16) float sW2[2][32 * 32];
    __shared__ __align__(16) float sb2[2][32];
    __shared__ __align__(16) float sW3[2][32];
    __shared__ float sb3[2];

    const int tid = threadIdx.x;

    // Stage weights (padded rows for aligned LDS.128)
    for (int i = tid; i < 36; i += 128)  { int r = i / 12, c = i % 12; sWe1[r][c] = (c < 10) ? We1[r * 10 + c] : 0.f; }
    for (int i = tid; i < 12; i += 128)  sbe1[i] = (i < 10) ? be1[i] : 0.f;
    for (int i = tid; i < 120; i += 128) { int r = i / 12, c = i % 12; sWe2[r][c] = (c < 10) ? We2[r * 10 + c] : 0.f; }
    for (int i = tid; i < 12; i += 128)  sbe2[i] = (i < 10) ? be2[i] : 0.f;
    for (int i = tid; i < 640; i += 128) { sW1[0][i] = Wf1[i]; sW1[1][i] = Wv1[i]; }
    for (int i = tid; i < 1024; i += 128){ sW2[0][i] = Wf2[i]; sW2[1][i] = Wv2[i]; }
    for (int i = tid; i < 32; i += 128)  { sb1[0][i] = bf1[i]; sb1[1][i] = bv1[i];
                                           sb2[0][i] = bf2[i]; sb2[1][i] = bv2[i];
                                           sW3[0][i] = Wf3[i]; sW3[1][i] = Wv3[i]; }
    if (tid == 0) { sb3[0] = bf3[0]; sb3[1] = bv3[0]; }
    __syncthreads();

    const int lane = tid & 31;
    const int sub  = lane & 3;          // lane within 4-lane action group
    const int grp  = tid >> 2;          // action group within block (0..31)
    const long long act = (long long)blockIdx.x * 32 + grp;
    const bool valid = act < n_act;
    const long long ai = valid ? act : (long long)(n_act - 1);  // clamp: keep all lanes live for shfl

    const float*  S  = Smat + ai * NATOM;
    const float4* R4 = reinterpret_cast<const float4*>(Rraw) + ai * NATOM;
    const float*  M  = Msk + ai * NATOM * 3;

    float A[2][4];
    float Bm[4][10];
    #pragma unroll
    for (int k = 0; k < 2; k++)
        #pragma unroll
        for (int l = 0; l < 4; l++) A[k][l] = 0.f;
    #pragma unroll
    for (int l = 0; l < 4; l++)
        #pragma unroll
        for (int n = 0; n < 10; n++) Bm[l][n] = 0.f;

    float g0[10], r0[4];   // atom-0 capture (valid on sub==0 after t==0; broadcast later)
    float gt[10], rt[4];

    // t = 0 pair: capture first atom's (g, r) -> on sub==0 that's atom 0
    proc_pair(S, R4, M, sub, 4 + sub, sWe1, sbe1, sWe2, sbe2, A, Bm, r0, g0);

    #pragma unroll
    for (int t = 2; t < 16; t += 2) {
        proc_pair(S, R4, M, t * 4 + sub, (t + 1) * 4 + sub,
                  sWe1, sbe1, sWe2, sbe2, A, Bm, rt, gt);
    }

    // Reduce A, Bm across the 4 lanes of the group
    #pragma unroll
    for (int k = 0; k < 2; k++)
        #pragma unroll
        for (int l = 0; l < 4; l++) {
            float v = A[k][l];
            v += __shfl_xor_sync(0xffffffffu, v, 1);
            v += __shfl_xor_sync(0xffffffffu, v, 2);
            A[k][l] = v;
        }
    #pragma unroll
    for (int l = 0; l < 4; l++)
        #pragma unroll
        for (int n = 0; n < 10; n++) {
            float v = Bm[l][n];
            v += __shfl_xor_sync(0xffffffffu, v, 1);
            v += __shfl_xor_sync(0xffffffffu, v, 2);
            Bm[l][n] = v;
        }

    // Broadcast atom-0 (g0, r0) from sub==0 to all lanes of the group
    #pragma unroll
    for (int j = 0; j < 10; j++) g0[j] = __shfl_sync(0xffffffffu, g0[j], 0, 4);
    #pragma unroll
    for (int l = 0; l < 4; l++)  r0[l] = __shfl_sync(0xffffffffu, r0[l], 0, 4);

    float outv = 0.f;
    if (sub < 2) {
        if (sub == 1) {
            // value head: exclude atom 0
            #pragma unroll
            for (int k = 0; k < 2; k++)
                #pragma unroll
                for (int l = 0; l < 4; l++) A[k][l] -= g0[k] * r0[l];
            #pragma unroll
            for (int l = 0; l < 4; l++)
                #pragma unroll
                for (int n = 0; n < 10; n++) Bm[l][n] -= r0[l] * g0[n];
        }

        // D = A @ Bm, flattened row-major [2*10]
        float x[20];
        #pragma unroll
        for (int k = 0; k < 2; k++)
            #pragma unroll
            for (int n = 0; n < 10; n++)
                x[k * 10 + n] = A[k][0] * Bm[0][n] + A[k][1] * Bm[1][n]
                              + A[k][2] * Bm[2][n] + A[k][3] * Bm[3][n];

        const float* W1 = sW1[sub];
        const float* B1 = sb1[sub];
        const float* W2 = sW2[sub];
        const float* B2 = sb2[sub];
        const float* W3 = sW3[sub];

        float hh[32];
        #pragma unroll
        for (int n = 0; n < 32; n++) hh[n] = B1[n];
        #pragma unroll
        for (int j = 0; j < 20; j++) {
            float xj = x[j];
            const float4* wr = reinterpret_cast<const float4*>(W1 + (j << 5));
            #pragma unroll
            for (int q = 0; q < 8; q++) {
                float4 w = wr[q];
                hh[q * 4 + 0] += xj * w.x;
                hh[q * 4 + 1] += xj * w.y;
                hh[q * 4 + 2] += xj * w.z;
                hh[q * 4 + 3] += xj * w.w;
            }
        }
        #pragma unroll
        for (int n = 0; n < 32; n++) hh[n] = fmaxf(hh[n], 0.f);

        float h2[32];
        #pragma unroll
        for (int n = 0; n < 32; n++) h2[n] = B2[n];
        #pragma unroll
        for (int j = 0; j < 32; j++) {
            float xj = hh[j];
            const float4* wr = reinterpret_cast<const float4*>(W2 + (j << 5));
            #pragma unroll
            for (int q = 0; q < 8; q++) {
                float4 w = wr[q];
                h2[q * 4 + 0] += xj * w.x;
                h2[q * 4 + 1] += xj * w.y;
                h2[q * 4 + 2] += xj * w.z;
                h2[q * 4 + 3] += xj * w.w;
            }
        }
        #pragma unroll
        for (int n = 0; n < 32; n++) h2[n] = fmaxf(h2[n], 0.f);

        float o = sb3[sub];
        #pragma unroll
        for (int n = 0; n < 32; n++) o += h2[n] * W3[n];
        outv = o;
    }

    if (valid && act < NMAX) {
        if (sub == 0)      d_lf[act] = outv;
        else if (sub == 1) d_lv[act] = outv;
    }
}

// ---------------------------------------------------------------------------
// Reductions: deterministic block partials (no float atomics)
// ---------------------------------------------------------------------------
__global__ void k_partial_maxsum(int n_act)
{
    __shared__ float smax[256];
    __shared__ float ssum[256];
    const int tid = threadIdx.x;
    float m = -3.0e38f, v = 0.f;
    for (int i = blockIdx.x * 256 + tid; i < n_act; i += gridDim.x * 256) {
        m = fmaxf(m, d_lf[i]);
        v += d_lv[i];
    }
    smax[tid] = m; ssum[tid] = v;
    __syncthreads();
    for (int s = 128; s > 0; s >>= 1) {
        if (tid < s) {
            smax[tid] = fmaxf(smax[tid], smax[tid + s]);
            ssum[tid] += ssum[tid + s];
        }
        __syncthreads();
    }
    if (tid == 0) {
        d_red[blockIdx.x]       = smax[0];
        d_red[256 + blockIdx.x] = ssum[0];
    }
}

__global__ void k_finish_maxsum()
{
    __shared__ float smax[256];
    __shared__ float ssum[256];
    const int tid = threadIdx.x;
    smax[tid] = d_red[tid];
    ssum[tid] = d_red[256 + tid];
    __syncthreads();
    for (int s = 128; s > 0; s >>= 1) {
        if (tid < s) {
            smax[tid] = fmaxf(smax[tid], smax[tid + s]);
            ssum[tid] += ssum[tid + s];
        }
        __syncthreads();
    }
    if (tid == 0) {
        d_scal[0] = smax[0];  // global max
        d_scal[1] = ssum[0];  // value sum
    }
}

__global__ void k_partial_expsum(int n_act)
{
    __shared__ float ssum[256];
    const int tid = threadIdx.x;
    const float gm = d_scal[0];
    float v = 0.f;
    for (int i = blockIdx.x * 256 + tid; i < n_act; i += gridDim.x * 256) {
        v += expf(d_lf[i] - gm);
    }
    ssum[tid] = v;
    __syncthreads();
    for (int s = 128; s > 0; s >>= 1) {
        if (tid < s) ssum[tid] += ssum[tid + s];
        __syncthreads();
    }
    if (tid == 0) d_red[512 + blockIdx.x] = ssum[0];
}

__global__ void k_finish_lse(float* __restrict__ out, int n_act, int out_size)
{
    __shared__ float ssum[256];
    const int tid = threadIdx.x;
    ssum[tid] = d_red[512 + tid];
    __syncthreads();
    for (int s = 128; s > 0; s >>= 1) {
        if (tid < s) ssum[tid] += ssum[tid + s];
        __syncthreads();
    }
    if (tid == 0) {
        d_scal[2] = d_scal[0] + logf(ssum[0]);  // logsumexp
        if (out_size > n_act) out[n_act] = d_scal[1];  // value scalar
    }
}

__global__ void k_policy(float* __restrict__ out, int n_act)
{
    const int i = blockIdx.x * 256 + threadIdx.x;
    if (i < n_act) out[i] = d_lf[i] - d_scal[2];
}

// ---------------------------------------------------------------------------
extern "C" void kernel_launch(void* const* d_in, const int* in_sizes, int n_in,
                              void* d_out, int out_size)
{
    const float* Smat = (const float*)d_in[0];
    const float* Rraw = (const float*)d_in[1];
    const float* Msk  = (const float*)d_in[2];
    const float* We1  = (const float*)d_in[3];
    const float* be1  = (const float*)d_in[4];
    const float* We2  = (const float*)d_in[5];
    const float* be2  = (const float*)d_in[6];
    const float* Wf1  = (const float*)d_in[7];
    const float* bf1  = (const float*)d_in[8];
    const float* Wf2  = (const float*)d_in[9];
    const float* bf2  = (const float*)d_in[10];
    const float* Wf3  = (const float*)d_in[11];
    const float* bf3  = (const float*)d_in[12];
    const float* Wv1  = (const float*)d_in[13];
    const float* bv1  = (const float*)d_in[14];
    const float* Wv2  = (const float*)d_in[15];
    const float* bv2  = (const float*)d_in[16];
    const float* Wv3  = (const float*)d_in[17];
    const float* bv3  = (const float*)d_in[18];

    int n_act = in_sizes[0] / NATOM;
    if (n_act > NMAX) n_act = NMAX;
    float* out = (float*)d_out;

    int nblk = (n_act + 31) / 32;
    desc_main_kernel<<<nblk, 128>>>(Smat, Rraw, Msk,
                                    We1, be1, We2, be2,
                                    Wf1, bf1, Wf2, bf2, Wf3, bf3,
                                    Wv1, bv1, Wv2, bv2, Wv3, bv3,
                                    n_act);
    k_partial_maxsum<<<256, 256>>>(n_act);
    k_finish_maxsum<<<1, 256>>>();
    k_partial_expsum<<<256, 256>>>(n_act);
    k_finish_lse<<<1, 256>>>(out, n_act, out_size);
    k_policy<<<(n_act + 255) / 256, 256>>>(out, n_act);
}